// round 8
// baseline (speedup 1.0000x reference)
#include <cuda_runtime.h>
#include <stdint.h>

// RasterTriangle_46566035423850 — fully sparse 2D formulation.
// out[p,q] = sum_k v(p,k) * H_k[q].  Both v(.,k) over p and H(.,k) over q are
// piecewise constant except within one-pixel ramps => per-k diff lists dv (over p)
// and dh (over q) each have <= ~7 entries, found by evaluating the EXACT reference
// fp32 formula inside analytically-located windows (+/-2 sample guard).
// Per warp: base row p0 built by scatter+scan, then rows advance incrementally.
// R8: each CTA = (batch, quarter) covering BOTH images (warps 0-1: hf, 2-3: ri)
//     so every CTA has identical cost -> no end-of-wave tail from hf/ri imbalance.

#define NTHREADS 128
#define NW 4
#define SEG 64    // rows per warp
#define MAXD 12   // max diffs per k per dim (true bound ~7)
#define KSLOTS 96 // 64 hf + 32 ri

__global__ void __launch_bounds__(NTHREADS)
raster_kernel(const float* __restrict__ iv0,
              const float* __restrict__ iv1,
              float* __restrict__ out)
{
    const double PI_D   = 3.141592653589793238462643383279502884;
    const double SIDE_D = (PI_D * 0.5) / 512.0;
    const float  S      = (float)SIDE_D;
    const float  STRIPF = (float)(PI_D * 0.5);
    const float  STOPF  = (float)(PI_D * 0.5 - SIDE_D);
    const float  stepx  = __fdiv_rn(STOPF, 511.0f);
    const float  stepy  = __fdiv_rn(-STOPF, 511.0f);
    const float  invA   = (float)(1.0 / (SIDE_D * SIDE_D));

    __shared__ __align__(16) float xs[KSLOTS], ys[KSLOTS];
    __shared__ __align__(16) float dhH[KSLOTS][MAXD];
    __shared__ __align__(16) float dvV[KSLOTS][MAXD];
    __shared__ __align__(16) short qH[KSLOTS][MAXD];
    __shared__ __align__(16) short pV[KSLOTS][MAXD];
    __shared__ int   cntH[KSLOTS], cntV[KSLOTS];
    __shared__ __align__(16) float Rbuf[NW][512];
    __shared__ __align__(16) float vbuf[NW][64];

    const int tid     = threadIdx.x;
    const int b       = blockIdx.x >> 2;   // batch
    const int quarter = blockIdx.x & 3;    // 128-row quarter

    // zero R scratch (4 warps x 512 floats)
    {
        float4* r4 = (float4*)&Rbuf[0][0];
        #pragma unroll
        for (int i = 0; i < 4; ++i)
            r4[tid * 4 + i] = make_float4(0.f, 0.f, 0.f, 0.f);
    }
    // load interval endpoints. slots [0,64): hf (concat semantics); [64,96): ri.
    if (tid < 32) {
        const float2 ab = ((const float2*)iv0)[b * 32 + tid];
        xs[tid] = ab.x;  ys[tid] = ab.y;                 // hf first half (a0, b0)
        xs[64 + tid] = ab.x;  ys[64 + tid] = ab.y;       // ri (a0, b0)
    } else if (tid < 64) {
        const float2 ab = ((const float2*)iv1)[b * 32 + (tid - 32)];
        xs[tid] = __fsub_rn(ab.y, STRIPF);               // b1 - STRIP
        ys[tid] = ab.x;                                  // a1
    }
    __syncthreads();

    // ---- Phase 1: per-(k, dim) windowed diff extraction (both images) ----
    for (int task = tid; task < 2 * KSLOTS; task += NTHREADS) {
        const int kk  = task >> 1;
        const int dim = task & 1;          // 0 = horizontal(q), 1 = vertical(p)
        const int img = (kk >= 64) ? 1 : 0;
        const float x = xs[kk], y = ys[kk];

        // analytic ramp windows (float sample coords)
        float w1lo, w1hi, w2lo, w2hi; int has2;
        if (dim == 0) {
            w1lo = __fdiv_rn(__fsub_rn(x, S), stepx);  w1hi = __fdiv_rn(x, stepx);
            w2lo = __fdiv_rn(__fsub_rn(y, S), stepx);  w2hi = __fdiv_rn(y, stepx);
            has2 = (img == 0);
        } else {
            w1lo = __fdiv_rn(__fsub_rn(STOPF, y), stepx);
            w1hi = __fdiv_rn(__fadd_rn(__fsub_rn(STOPF, y), S), stepx);
            const float t = __fsub_rn(__fsub_rn(STOPF, x), STRIPF);
            w2lo = __fdiv_rn(t, stepx);
            w2hi = __fdiv_rn(__fadd_rn(t, S), stepx);
            has2 = (img == 0);
        }

        int aLo = 0, aHi = -1, bLo = 0, bHi = -1;
        {
            const int lo = (int)floorf(w1lo) - 2, hi = (int)ceilf(w1hi) + 2;
            if (lo <= 511) { aLo = max(lo, 0); aHi = min(511, max(hi, 0)); }
        }
        if (has2) {
            const int lo = (int)floorf(w2lo) - 2, hi = (int)ceilf(w2hi) + 2;
            if (lo <= 511) { bLo = max(lo, 0); bHi = min(511, max(hi, 0)); }
        }
        if (aHi < aLo) { aLo = bLo; aHi = bHi; bHi = -1; }      // A empty -> use B
        if (bHi >= bLo) {                                        // both nonempty
            if (bLo < aLo) { int t;                              // order by lo
                t = aLo; aLo = bLo; bLo = t;  t = aHi; aHi = bHi; bHi = t; }
            if (bLo <= aHi + 1) { aHi = max(aHi, bHi); bHi = -1; }   // merge
        }

        short* qq = dim ? pV[kk] : qH[kk];
        float* dd = dim ? dvV[kk] : dhH[kk];
        int cnt = 0;
        #pragma unroll 1
        for (int sp = 0; sp < 2; ++sp) {
            const int lo = sp ? bLo : aLo, hi = sp ? bHi : aHi;
            if (hi < lo) continue;
            float prev = 0.f;
            for (int t = (lo == 0 ? 0 : lo - 1); t <= hi; ++t) {
                float f;
                if (dim == 0) {
                    const float px = __fmul_rn((float)t, stepx);
                    const float A  = __fsub_rn(__fadd_rn(px, S), x);
                    const float m  = img ? A : fminf(A, __fsub_rn(y, px));
                    f = fmaxf(fminf(S, m), 0.f);
                } else {
                    const float py = __fadd_rn(STOPF, __fmul_rn((float)t, stepy));
                    float m;
                    if (img) m = __fsub_rn(y, py);
                    else m = fminf(__fsub_rn(__fadd_rn(py, S), y),
                                   __fsub_rn(__fadd_rn(x, STRIPF), py));
                    f = fmaxf(fminf(S, m), 0.f);
                }
                if (t >= lo && f != prev && cnt < MAXD) {
                    qq[cnt] = (short)t;
                    dd[cnt] = dim ? __fmul_rn(__fsub_rn(f, prev), invA)
                                  : __fsub_rn(f, prev);
                    ++cnt;
                }
                prev = f;
            }
        }
        (dim ? cntV : cntH)[kk] = cnt;
    }
    __syncthreads();

    // ---- Phase 2: warps 0-1 -> hf (64 rows each), warps 2-3 -> ri ----
    const int warp = tid >> 5;
    const int lane = tid & 31;
    const int wimg = warp >> 1;                 // 0 = hf, 1 = ri
    const int koff = wimg ? 64 : 0;
    const int K    = wimg ? 32 : 64;
    const int p0   = (quarter << 7) + ((warp & 1) << 6);
    const int imgslot = (b << 1) + wimg;
    float* const R = Rbuf[warp];

    // v(p0, k) * invA  (closed form, identical ops to reference)
    {
        const float py = __fadd_rn(STOPF, __fmul_rn((float)p0, stepy));
        {
            const float x = xs[koff + lane], y = ys[koff + lane];
            float m;
            if (wimg) m = __fsub_rn(y, py);
            else m = fminf(__fsub_rn(__fadd_rn(py, S), y),
                           __fsub_rn(__fadd_rn(x, STRIPF), py));
            vbuf[warp][lane] = fmaxf(fminf(S, m), 0.f) * invA;
        }
        if (!wimg) {
            const float x = xs[lane + 32], y = ys[lane + 32];
            const float m = fminf(__fsub_rn(__fadd_rn(py, S), y),
                                  __fsub_rn(__fadd_rn(x, STRIPF), py));
            vbuf[warp][lane + 32] = fmaxf(fminf(S, m), 0.f) * invA;
        }
    }
    __syncwarp();

    // base row: R[q] += v(p0,k) * dh  (lane j handles entry j of k; serial over k)
    for (int k = 0; k < K; ++k) {
        const float v = vbuf[warp][k];     // broadcast
        if (v != 0.f) {
            const int kg = koff + k;
            if (lane < cntH[kg]) {
                const int q = qH[kg][lane];
                R[q] = __fmaf_rn(v, dhH[kg][lane], R[q]);
            }
            __syncwarp();
        }
    }

    // dv cursors: lane owns k0g = koff+lane (and k1g = lane+32 for hf)
    const int k0g = koff + lane, k1g = lane + 32;
    const int c0 = cntV[k0g];
    const int c1 = (wimg == 0) ? cntV[k1g] : 0;
    int cur0 = 0; while (cur0 < c0 && pV[k0g][cur0] <= p0) ++cur0;
    int cur1 = 0; while (cur1 < c1 && pV[k1g][cur1] <= p0) ++cur1;
    int np0 = (cur0 < c0) ? pV[k0g][cur0] : (1 << 30);
    int np1 = (cur1 < c1) ? pV[k1g][cur1] : (1 << 30);

    float O[16];
    #pragma unroll
    for (int i = 0; i < 16; ++i) O[i] = 0.f;

    float* orow = out + ((size_t)imgslot << 18) + ((size_t)p0 << 9);

    for (int p = p0; p < p0 + SEG; ++p) {
        bool doscan = (p == p0);
        if (p > p0) {
            const bool m0 = (np0 == p), m1 = (np1 == p);
            unsigned bal0 = __ballot_sync(0xFFFFFFFFu, m0);
            unsigned bal1 = __ballot_sync(0xFFFFFFFFu, m1);
            float dv0 = 0.f, dv1 = 0.f;
            if (m0) { dv0 = dvV[k0g][cur0]; ++cur0;
                      np0 = (cur0 < c0) ? pV[k0g][cur0] : (1 << 30); }
            if (m1) { dv1 = dvV[k1g][cur1]; ++cur1;
                      np1 = (cur1 < c1) ? pV[k1g][cur1] : (1 << 30); }
            if (bal0 | bal1) {
                doscan = true;
                while (bal0) {
                    const int src = __ffs(bal0) - 1; bal0 &= bal0 - 1;
                    const float dv = __shfl_sync(0xFFFFFFFFu, dv0, src);
                    const int kg = koff + src;
                    if (lane < cntH[kg]) {
                        const int q = qH[kg][lane];
                        R[q] = __fmaf_rn(dv, dhH[kg][lane], R[q]);
                    }
                    __syncwarp();
                }
                while (bal1) {
                    const int src = __ffs(bal1) - 1; bal1 &= bal1 - 1;
                    const float dv = __shfl_sync(0xFFFFFFFFu, dv1, src);
                    const int kg = src + 32;
                    if (lane < cntH[kg]) {
                        const int q = qH[kg][lane];
                        R[q] = __fmaf_rn(dv, dhH[kg][lane], R[q]);
                    }
                    __syncwarp();
                }
            }
        }
        if (doscan) {
            __syncwarp();
            float carry = 0.f;
            float4* r4 = (float4*)R;
            #pragma unroll
            for (int m = 0; m < 4; ++m) {
                float4 c = r4[m * 32 + lane];
                r4[m * 32 + lane] = make_float4(0.f, 0.f, 0.f, 0.f);  // clear for next row
                c.y += c.x; c.z += c.y; c.w += c.z;
                const float t = c.w;
                float incl = t;
                #pragma unroll
                for (int d = 1; d < 32; d <<= 1) {
                    const float s = __shfl_up_sync(0xFFFFFFFFu, incl, d);
                    if (lane >= d) incl += s;
                }
                const float add = incl - t + carry;
                O[4 * m + 0] += c.x + add;
                O[4 * m + 1] += c.y + add;
                O[4 * m + 2] += c.z + add;
                O[4 * m + 3] += c.w + add;
                carry += __shfl_sync(0xFFFFFFFFu, incl, 31);
            }
            __syncwarp();
        }
        // coalesced streaming row store (always)
        __stcs((float4*)(orow) + lane +  0, make_float4(O[0],  O[1],  O[2],  O[3]));
        __stcs((float4*)(orow) + lane + 32, make_float4(O[4],  O[5],  O[6],  O[7]));
        __stcs((float4*)(orow) + lane + 64, make_float4(O[8],  O[9],  O[10], O[11]));
        __stcs((float4*)(orow) + lane + 96, make_float4(O[12], O[13], O[14], O[15]));
        orow += 512;
    }
}

extern "C" void kernel_launch(void* const* d_in, const int* in_sizes, int n_in,
                              void* d_out, int out_size)
{
    const float* iv0 = (const float*)d_in[0];   // intervals00: (256, 32, 2) f32
    const float* iv1 = (const float*)d_in[1];   // intervals01: (256, 32, 2) f32
    float* out = (float*)d_out;                 // (256, 2, 512, 512) f32
    (void)in_sizes; (void)n_in; (void)out_size;
    raster_kernel<<<1024, NTHREADS>>>(iv0, iv1, out);
}

// round 9
// speedup vs baseline: 1.1338x; 1.1338x over previous
#include <cuda_runtime.h>
#include <stdint.h>

// RasterTriangle_46566035423850 — fully sparse 2D formulation.
// out[p,q] = sum_k v(p,k) * H_k[q].  Both v(.,k) over p and H(.,k) over q are
// piecewise constant except within one-pixel ramps => per-k diff lists dv (over p)
// and dh (over q) each have <= ~7 entries, found by evaluating the EXACT reference
// fp32 formula inside analytically-located windows (+/-2 sample guard).
// Per warp: base row p0 built by scatter+scan, then rows advance incrementally:
//   out[p,:] = out[p-1,:] + prefix_q( sum_{k: dv at p} dv * dH_k )   (usually zero).
// R9: 64-row-slice CTAs (4 warps x SEG 16), grid 4096 -> fine-grain waves, small tail.

#define NTHREADS 128
#define NW 4
#define SEG 16    // rows per warp
#define MAXD 12   // max diffs per k per dim (true bound ~7)

__global__ void __launch_bounds__(NTHREADS)
raster_kernel(const float* __restrict__ iv0,
              const float* __restrict__ iv1,
              float* __restrict__ out)
{
    const double PI_D   = 3.141592653589793238462643383279502884;
    const double SIDE_D = (PI_D * 0.5) / 512.0;
    const float  S      = (float)SIDE_D;
    const float  STRIPF = (float)(PI_D * 0.5);
    const float  STOPF  = (float)(PI_D * 0.5 - SIDE_D);
    const float  stepx  = __fdiv_rn(STOPF, 511.0f);
    const float  stepy  = __fdiv_rn(-STOPF, 511.0f);
    const float  invA   = (float)(1.0 / (SIDE_D * SIDE_D));

    __shared__ __align__(16) float xs[64], ys[64];
    __shared__ __align__(16) float dhH[64][MAXD];
    __shared__ __align__(16) float dvV[64][MAXD];
    __shared__ __align__(16) short qH[64][MAXD];
    __shared__ __align__(16) short pV[64][MAXD];
    __shared__ int   cntH[64], cntV[64];
    __shared__ __align__(16) float Rbuf[NW][512];
    __shared__ __align__(16) float vbuf[NW][64];

    const int tid     = threadIdx.x;
    const int imgslot = blockIdx.x >> 3;   // 0..511 = b*2 + img
    const int eighth  = blockIdx.x & 7;    // which 64-row slice
    const int img     = imgslot & 1;
    const int b       = imgslot >> 1;
    const int K       = img ? 32 : 64;

    // zero R scratch (4 warps x 512 floats)
    {
        float4* r4 = (float4*)&Rbuf[0][0];
        #pragma unroll
        for (int i = 0; i < 4; ++i)
            r4[tid * 4 + i] = make_float4(0.f, 0.f, 0.f, 0.f);
    }
    // load interval endpoints (reference's concat semantics)
    if (tid < 32) {
        const float2 ab = ((const float2*)iv0)[b * 32 + tid];
        xs[tid] = ab.x;  ys[tid] = ab.y;                 // (a0, b0)
    } else if (tid < 64 && img == 0) {
        const float2 ab = ((const float2*)iv1)[b * 32 + (tid - 32)];
        xs[tid] = __fsub_rn(ab.y, STRIPF);               // b1 - STRIP
        ys[tid] = ab.x;                                  // a1
    }
    __syncthreads();

    // ---- Phase 1: per-(k, dim) windowed diff extraction ----
    if (tid < 2 * K) {
        const int k   = tid >> 1;
        const int dim = tid & 1;     // 0 = horizontal(q), 1 = vertical(p)
        const float x = xs[k], y = ys[k];

        // analytic ramp windows (float sample coords)
        float w1lo, w1hi, w2lo, w2hi; int has2;
        if (dim == 0) {
            w1lo = __fdiv_rn(__fsub_rn(x, S), stepx);  w1hi = __fdiv_rn(x, stepx);
            w2lo = __fdiv_rn(__fsub_rn(y, S), stepx);  w2hi = __fdiv_rn(y, stepx);
            has2 = (img == 0);
        } else {
            w1lo = __fdiv_rn(__fsub_rn(STOPF, y), stepx);
            w1hi = __fdiv_rn(__fadd_rn(__fsub_rn(STOPF, y), S), stepx);
            const float t = __fsub_rn(__fsub_rn(STOPF, x), STRIPF);
            w2lo = __fdiv_rn(t, stepx);
            w2hi = __fdiv_rn(__fadd_rn(t, S), stepx);
            has2 = (img == 0);
        }

        int aLo = 0, aHi = -1, bLo = 0, bHi = -1;
        {
            const int lo = (int)floorf(w1lo) - 2, hi = (int)ceilf(w1hi) + 2;
            if (lo <= 511) { aLo = max(lo, 0); aHi = min(511, max(hi, 0)); }
        }
        if (has2) {
            const int lo = (int)floorf(w2lo) - 2, hi = (int)ceilf(w2hi) + 2;
            if (lo <= 511) { bLo = max(lo, 0); bHi = min(511, max(hi, 0)); }
        }
        if (aHi < aLo) { aLo = bLo; aHi = bHi; bHi = -1; }      // A empty -> use B
        if (bHi >= bLo) {                                        // both nonempty
            if (bLo < aLo) { int t;                              // order by lo
                t = aLo; aLo = bLo; bLo = t;  t = aHi; aHi = bHi; bHi = t; }
            if (bLo <= aHi + 1) { aHi = max(aHi, bHi); bHi = -1; }   // merge
        }

        short* qq = dim ? pV[k] : qH[k];
        float* dd = dim ? dvV[k] : dhH[k];
        int cnt = 0;
        #pragma unroll 1
        for (int sp = 0; sp < 2; ++sp) {
            const int lo = sp ? bLo : aLo, hi = sp ? bHi : aHi;
            if (hi < lo) continue;
            float prev = 0.f;
            for (int t = (lo == 0 ? 0 : lo - 1); t <= hi; ++t) {
                float f;
                if (dim == 0) {
                    const float px = __fmul_rn((float)t, stepx);
                    const float A  = __fsub_rn(__fadd_rn(px, S), x);
                    const float m  = img ? A : fminf(A, __fsub_rn(y, px));
                    f = fmaxf(fminf(S, m), 0.f);
                } else {
                    const float py = __fadd_rn(STOPF, __fmul_rn((float)t, stepy));
                    float m;
                    if (img) m = __fsub_rn(y, py);
                    else m = fminf(__fsub_rn(__fadd_rn(py, S), y),
                                   __fsub_rn(__fadd_rn(x, STRIPF), py));
                    f = fmaxf(fminf(S, m), 0.f);
                }
                if (t >= lo && f != prev && cnt < MAXD) {
                    qq[cnt] = (short)t;
                    dd[cnt] = dim ? __fmul_rn(__fsub_rn(f, prev), invA)
                                  : __fsub_rn(f, prev);
                    ++cnt;
                }
                prev = f;
            }
        }
        (dim ? cntV : cntH)[k] = cnt;
    }
    __syncthreads();

    // ---- Phase 2: per-warp segment of SEG rows ----
    const int warp = tid >> 5;
    const int lane = tid & 31;
    const int p0   = (eighth << 6) + warp * SEG;
    float* const R = Rbuf[warp];

    // v(p0, k) * invA  (closed form, identical ops to reference)
    {
        const float py = __fadd_rn(STOPF, __fmul_rn((float)p0, stepy));
        {
            const float x = xs[lane], y = ys[lane];
            float m;
            if (img) m = __fsub_rn(y, py);
            else m = fminf(__fsub_rn(__fadd_rn(py, S), y),
                           __fsub_rn(__fadd_rn(x, STRIPF), py));
            vbuf[warp][lane] = fmaxf(fminf(S, m), 0.f) * invA;
        }
        if (!img) {
            const float x = xs[lane + 32], y = ys[lane + 32];
            const float m = fminf(__fsub_rn(__fadd_rn(py, S), y),
                                  __fsub_rn(__fadd_rn(x, STRIPF), py));
            vbuf[warp][lane + 32] = fmaxf(fminf(S, m), 0.f) * invA;
        }
    }
    __syncwarp();

    // base row: R[q] += v(p0,k) * dh  (lane j handles entry j of k; serial over k)
    for (int k = 0; k < K; ++k) {
        const float v = vbuf[warp][k];     // broadcast
        if (v != 0.f) {
            if (lane < cntH[k]) {
                const int q = qH[k][lane];
                R[q] = __fmaf_rn(v, dhH[k][lane], R[q]);
            }
            __syncwarp();
        }
    }

    // dv cursors: lane owns k0 = lane (and k1 = lane+32 for hf)
    const int k0 = lane, k1 = lane + 32;
    const int c0 = cntV[k0];
    const int c1 = (img == 0) ? cntV[k1] : 0;
    int cur0 = 0; while (cur0 < c0 && pV[k0][cur0] <= p0) ++cur0;
    int cur1 = 0; while (cur1 < c1 && pV[k1][cur1] <= p0) ++cur1;
    int np0 = (cur0 < c0) ? pV[k0][cur0] : (1 << 30);
    int np1 = (cur1 < c1) ? pV[k1][cur1] : (1 << 30);

    float O[16];
    #pragma unroll
    for (int i = 0; i < 16; ++i) O[i] = 0.f;

    float* orow = out + ((size_t)imgslot << 18) + ((size_t)p0 << 9);

    for (int p = p0; p < p0 + SEG; ++p) {
        bool doscan = (p == p0);
        if (p > p0) {
            const bool m0 = (np0 == p), m1 = (np1 == p);
            unsigned bal0 = __ballot_sync(0xFFFFFFFFu, m0);
            unsigned bal1 = __ballot_sync(0xFFFFFFFFu, m1);
            float dv0 = 0.f, dv1 = 0.f;
            if (m0) { dv0 = dvV[k0][cur0]; ++cur0;
                      np0 = (cur0 < c0) ? pV[k0][cur0] : (1 << 30); }
            if (m1) { dv1 = dvV[k1][cur1]; ++cur1;
                      np1 = (cur1 < c1) ? pV[k1][cur1] : (1 << 30); }
            if (bal0 | bal1) {
                doscan = true;
                while (bal0) {
                    const int src = __ffs(bal0) - 1; bal0 &= bal0 - 1;
                    const float dv = __shfl_sync(0xFFFFFFFFu, dv0, src);
                    if (lane < cntH[src]) {
                        const int q = qH[src][lane];
                        R[q] = __fmaf_rn(dv, dhH[src][lane], R[q]);
                    }
                    __syncwarp();
                }
                while (bal1) {
                    const int src = __ffs(bal1) - 1; bal1 &= bal1 - 1;
                    const float dv = __shfl_sync(0xFFFFFFFFu, dv1, src);
                    const int k = src + 32;
                    if (lane < cntH[k]) {
                        const int q = qH[k][lane];
                        R[q] = __fmaf_rn(dv, dhH[k][lane], R[q]);
                    }
                    __syncwarp();
                }
            }
        }
        if (doscan) {
            __syncwarp();
            float carry = 0.f;
            float4* r4 = (float4*)R;
            #pragma unroll
            for (int m = 0; m < 4; ++m) {
                float4 c = r4[m * 32 + lane];
                r4[m * 32 + lane] = make_float4(0.f, 0.f, 0.f, 0.f);  // clear for next row
                c.y += c.x; c.z += c.y; c.w += c.z;
                const float t = c.w;
                float incl = t;
                #pragma unroll
                for (int d = 1; d < 32; d <<= 1) {
                    const float s = __shfl_up_sync(0xFFFFFFFFu, incl, d);
                    if (lane >= d) incl += s;
                }
                const float add = incl - t + carry;
                O[4 * m + 0] += c.x + add;
                O[4 * m + 1] += c.y + add;
                O[4 * m + 2] += c.z + add;
                O[4 * m + 3] += c.w + add;
                carry += __shfl_sync(0xFFFFFFFFu, incl, 31);
            }
            __syncwarp();
        }
        // coalesced streaming row store (always)
        __stcs((float4*)(orow) + lane +  0, make_float4(O[0],  O[1],  O[2],  O[3]));
        __stcs((float4*)(orow) + lane + 32, make_float4(O[4],  O[5],  O[6],  O[7]));
        __stcs((float4*)(orow) + lane + 64, make_float4(O[8],  O[9],  O[10], O[11]));
        __stcs((float4*)(orow) + lane + 96, make_float4(O[12], O[13], O[14], O[15]));
        orow += 512;
    }
}

extern "C" void kernel_launch(void* const* d_in, const int* in_sizes, int n_in,
                              void* d_out, int out_size)
{
    const float* iv0 = (const float*)d_in[0];   // intervals00: (256, 32, 2) f32
    const float* iv1 = (const float*)d_in[1];   // intervals01: (256, 32, 2) f32
    float* out = (float*)d_out;                 // (256, 2, 512, 512) f32
    (void)in_sizes; (void)n_in; (void)out_size;
    raster_kernel<<<4096, NTHREADS>>>(iv0, iv1, out);
}